// round 5
// baseline (speedup 1.0000x reference)
#include <cuda_runtime.h>
#include <cstdint>

// Problem constants
#define TQ 4096   // tokens
#define HD 1024   // hidden
#define FD 2048   // ffn dim (w1 rows: [gate(0..FD), up(FD..2FD)])
#define NE 8      // experts
#define NK 2      // top-k

// ---------------------------------------------------------------------------
// Scratch (device globals; runtime allocation is forbidden)
// ---------------------------------------------------------------------------
__device__ int   g_counts[NE];
__device__ int   g_tok[NE * TQ];
__device__ float g_wt[TQ * NK];
__device__ float g_act[(size_t)TQ * NK * FD];        // tf32-rounded silu(g)*u
__device__ float g_y[(size_t)TQ * NK * HD];
__device__ float g_hst[(size_t)TQ * HD];             // tf32-rounded hs
__device__ float g_w1t[(size_t)NE * 2 * FD * HD];    // tf32-rounded w1
__device__ float g_w2t[(size_t)NE * HD * FD];        // tf32-rounded w2

// ---------------------------------------------------------------------------
// Helpers
// ---------------------------------------------------------------------------
__device__ __forceinline__ uint32_t f2tf(float x) {
    uint32_t r;
    asm("cvt.rna.tf32.f32 %0, %1;" : "=r"(r) : "f"(x));
    return r;
}
__device__ __forceinline__ uint32_t s2u(const void* p) {
    uint32_t a;
    asm("{ .reg .u64 t; cvta.to.shared.u64 t, %1; cvt.u32.u64 %0, t; }"
        : "=r"(a) : "l"(p));
    return a;
}
__device__ __forceinline__ void mma_tf32(float* c, const uint32_t* a,
                                         uint32_t b0, uint32_t b1) {
    asm volatile(
        "mma.sync.aligned.m16n8k8.row.col.f32.tf32.tf32.f32 "
        "{%0,%1,%2,%3}, {%4,%5,%6,%7}, {%8,%9}, {%0,%1,%2,%3};"
        : "+f"(c[0]), "+f"(c[1]), "+f"(c[2]), "+f"(c[3])
        : "r"(a[0]), "r"(a[1]), "r"(a[2]), "r"(a[3]), "r"(b0), "r"(b1));
}
// ldmatrix x4 over b16: with 16B rows = 4 tf32, lane receives tf32
// element [lane/4][lane%4] of each 8x4 matrix — exactly the mma frag layout.
__device__ __forceinline__ void ldsm4(uint32_t* r, uint32_t addr) {
    asm volatile("ldmatrix.sync.aligned.m8n8.x4.shared.b16 {%0,%1,%2,%3}, [%4];"
                 : "=r"(r[0]), "=r"(r[1]), "=r"(r[2]), "=r"(r[3]) : "r"(addr));
}
__device__ __forceinline__ float silu(float x) {
    return x / (1.0f + __expf(-x));
}

// 16B cp.async with zero-fill when sz==0 (invalid A rows)
#define CPA16(sa, ga, sz)                                                      \
    asm volatile("cp.async.cg.shared.global [%0], [%1], 16, %2;"               \
                 :: "r"(sa), "l"(ga), "r"(sz) : "memory")

// Stage layout: A 128x32 floats (16KB) then B 256x32 floats (32KB) = 48KB.
// Swizzle: physical 16B-chunk = chunk ^ (row & 7).
#define STAGE_BYTES 49152u

#define LOAD_STAGE(KC, ST) do {                                                \
    uint32_t _b = sbase + (uint32_t)(ST) * STAGE_BYTES;                        \
    const float* _a = aptr + (KC);                                             \
    const float* _w = bptr + (KC);                                             \
    _Pragma("unroll")                                                          \
    for (int _c = 0; _c < 4; _c++)                                             \
        CPA16(_b + offA[_c], _a + _c * 4, za);                                 \
    _Pragma("unroll")                                                          \
    for (int _c = 0; _c < 8; _c++)                                             \
        CPA16(_b + 16384u + offB[_c], _w + _c * 4, 16u);                       \
    asm volatile("cp.async.commit_group;" ::: "memory");                       \
} while (0)

// Fragment-load + MMA for one K-chunk. Warp tile 64x64: 4 mi x 8 ni.
#define CHUNK_MMA(IST) do {                                                    \
    uint32_t _sA = sbase + (uint32_t)(IST) * STAGE_BYTES;                      \
    uint32_t _sB = _sA + 16384u;                                               \
    _Pragma("unroll")                                                          \
    for (int ks = 0; ks < 4; ks++) {                                           \
        uint32_t br[4][4];                                                     \
        _Pragma("unroll")                                                      \
        for (int nip = 0; nip < 4; nip++)                                      \
            ldsm4(br[nip], _sB + aoffB + nip * 2048u + xb[ks]);                \
        uint32_t ar[4][4];                                                     \
        _Pragma("unroll")                                                      \
        for (int mi = 0; mi < 4; mi++)                                         \
            ldsm4(ar[mi], _sA + aoffA + mi * 2048u + xa[ks]);                  \
        _Pragma("unroll")                                                      \
        for (int mi = 0; mi < 4; mi++)                                         \
            _Pragma("unroll")                                                  \
            for (int ni = 0; ni < 8; ni++)                                     \
                mma_tf32(acc[mi][ni], ar[mi],                                  \
                         br[ni >> 1][2 * (ni & 1)],                            \
                         br[ni >> 1][2 * (ni & 1) + 1]);                       \
    }                                                                          \
} while (0)

// ---------------------------------------------------------------------------
// Kernel 0: zero per-expert counts
// ---------------------------------------------------------------------------
__global__ void k_zero() {
    if (threadIdx.x < NE) g_counts[threadIdx.x] = 0;
}

// ---------------------------------------------------------------------------
// Kernel 0b: tf32-round a tensor into scratch
// ---------------------------------------------------------------------------
__global__ __launch_bounds__(256) void k_cvt(const float4* __restrict__ src,
                                             float4* __restrict__ dst, int n4) {
    int i = blockIdx.x * 256 + threadIdx.x;
    if (i >= n4) return;
    float4 v = src[i];
    float4 o;
    o.x = __uint_as_float(f2tf(v.x));
    o.y = __uint_as_float(f2tf(v.y));
    o.z = __uint_as_float(f2tf(v.z));
    o.w = __uint_as_float(f2tf(v.w));
    dst[i] = o;
}

// ---------------------------------------------------------------------------
// Kernel 1: router. One warp per token.
// ---------------------------------------------------------------------------
__global__ __launch_bounds__(256) void k_router(const float* __restrict__ hs,
                                                const float* __restrict__ gw,
                                                float* __restrict__ logits_out) {
    __shared__ float sg[NE * HD];
    int tid = threadIdx.x;
    for (int i = tid; i < NE * HD; i += 256) sg[i] = gw[i];
    __syncthreads();

    int warp = tid >> 5, lane = tid & 31;
    int t = blockIdx.x * 8 + warp;
    const float* x = hs + (size_t)t * HD;

    float acc[NE];
#pragma unroll
    for (int e = 0; e < NE; e++) acc[e] = 0.f;
    for (int j = lane; j < HD; j += 32) {
        float xv = x[j];
#pragma unroll
        for (int e = 0; e < NE; e++) acc[e] += xv * sg[e * HD + j];
    }
#pragma unroll
    for (int e = 0; e < NE; e++) {
#pragma unroll
        for (int off = 16; off; off >>= 1)
            acc[e] += __shfl_xor_sync(0xffffffffu, acc[e], off);
    }

    if (lane == 0) {
        if (logits_out) {
#pragma unroll
            for (int e = 0; e < NE; e++) logits_out[(size_t)t * NE + e] = acc[e];
        }
        float m1 = acc[0]; int i0 = 0;
#pragma unroll
        for (int e = 1; e < NE; e++) if (acc[e] > m1) { m1 = acc[e]; i0 = e; }
        float m2 = -3.4e38f; int i1 = 0;
#pragma unroll
        for (int e = 0; e < NE; e++)
            if (e != i0 && acc[e] > m2) { m2 = acc[e]; i1 = e; }
        float e2v = __expf(m2 - m1);
        float inv = 1.0f / (1.0f + e2v);

        int p0 = atomicAdd(&g_counts[i0], 1);
        g_tok[i0 * TQ + p0] = t * 2;
        g_wt[t * 2] = inv;
        int p1 = atomicAdd(&g_counts[i1], 1);
        g_tok[i1 * TQ + p1] = t * 2 + 1;
        g_wt[t * 2 + 1] = e2v * inv;
    }
}

// ---------------------------------------------------------------------------
// Kernel 2: FFN1 grouped GEMM with fused SiLU*up.
// CTA tile 128 rows x 256 mma cols (128 logical gate cols, gate/up
// interleaved). Warp tile 64x64 (2x4 warp grid). 3-stage cp.async pipeline.
// grid = (FD/128 = 16, NE*32), 256 threads, 1 CTA/SM.
// ---------------------------------------------------------------------------
__global__ __launch_bounds__(256, 1) void k_ffn1() {
    int e  = blockIdx.y >> 5;
    int mt = blockIdx.y & 31;
    int cnt = g_counts[e];
    int m0 = mt * 128;
    if (m0 >= cnt) return;
    int n0 = blockIdx.x * 128;          // logical gate-column base

    extern __shared__ char dsm[];
    __shared__ int s_tok[128];

    int tid = threadIdx.x;
    if (tid < 128) {
        int idx = m0 + tid;
        s_tok[tid] = (idx < cnt) ? g_tok[e * TQ + idx] : -1;
    }
    __syncthreads();

    int warp = tid >> 5, lane = tid & 31;
    int wm = warp >> 2, wn = warp & 3;      // 2x4 warps, warp tile 64x64
    int g = lane >> 2, tg = lane & 3;

    // A loader: 2 threads per row (128 rows), 4 x 16B each
    int lrowA = tid >> 1, cbA = (tid & 1) * 4;
    int atok = s_tok[lrowA];
    uint32_t za = (atok >= 0) ? 16u : 0u;
    const float* aptr = g_hst + (size_t)(atok >= 0 ? (atok >> 1) : 0) * HD + cbA * 4;
    // B loader: 1 thread per row (256 rows = interleaved gate/up), 8 x 16B
    int wrow = (tid & 1) ? (FD + n0 + (tid >> 1)) : (n0 + (tid >> 1));
    const float* bptr = g_w1t + ((size_t)e * 2 * FD + wrow) * HD;

    uint32_t sbase = s2u(dsm);
    uint32_t offA[4], offB[8];
#pragma unroll
    for (int c = 0; c < 4; c++)
        offA[c] = (uint32_t)((lrowA * 32 + (((cbA + c) ^ (lrowA & 7)) << 2)) * 4);
#pragma unroll
    for (int c = 0; c < 8; c++)
        offB[c] = (uint32_t)((tid * 32 + ((c ^ (tid & 7)) << 2)) * 4);

    // ldmatrix per-lane address components
    int j = lane >> 3, r = lane & 7;
    uint32_t aoffA = (uint32_t)((wm * 64 + ((j & 1) << 3) + r) * 128);
    uint32_t aoffB = (uint32_t)((wn * 64 + ((j >> 1) << 3) + r) * 128);
    int cjA = j >> 1, cjB = j & 1;
    uint32_t xa[4], xb[4];
#pragma unroll
    for (int ks = 0; ks < 4; ks++) {
        xa[ks] = (uint32_t)((((2 * ks + cjA) ^ r) << 4));
        xb[ks] = (uint32_t)((((2 * ks + cjB) ^ r) << 4));
    }

    float acc[4][8][4];
#pragma unroll
    for (int mi = 0; mi < 4; mi++)
#pragma unroll
        for (int ni = 0; ni < 8; ni++)
#pragma unroll
            for (int q = 0; q < 4; q++) acc[mi][ni][q] = 0.f;

    const int NKC = HD / 32;   // 32
    LOAD_STAGE(0, 0);
    LOAD_STAGE(32, 1);

    for (int i = 0; i < NKC; i++) {
        asm volatile("cp.async.wait_group 1;" ::: "memory");
        __syncthreads();
        if (i + 2 < NKC) {
            int st = (i + 2) % 3;
            LOAD_STAGE((i + 2) * 32, st);
        } else {
            asm volatile("cp.async.commit_group;" ::: "memory");
        }
        CHUNK_MMA(i % 3);
    }

    // Epilogue: even mma col = gate, odd = up; write tf32-rounded activation.
#pragma unroll
    for (int mi = 0; mi < 4; mi++) {
        int rl0 = wm * 64 + mi * 16 + g;
        int t0 = s_tok[rl0], t1 = s_tok[rl0 + 8];
#pragma unroll
        for (int ni = 0; ni < 8; ni++) {
            int colg = n0 + wn * 32 + ni * 4 + tg;
            float* c = acc[mi][ni];
            if (t0 >= 0)
                g_act[(size_t)t0 * FD + colg] =
                    __uint_as_float(f2tf(silu(c[0]) * c[1]));
            if (t1 >= 0)
                g_act[(size_t)t1 * FD + colg] =
                    __uint_as_float(f2tf(silu(c[2]) * c[3]));
        }
    }
}

// ---------------------------------------------------------------------------
// Kernel 3: FFN2 grouped GEMM (act @ w2[e]^T), scaled by combine weight.
// CTA tile 128 x 256, warp tile 64x64. grid = (HD/256 = 4, NE*32).
// ---------------------------------------------------------------------------
__global__ __launch_bounds__(256, 1) void k_ffn2() {
    int e  = blockIdx.y >> 5;
    int mt = blockIdx.y & 31;
    int cnt = g_counts[e];
    int m0 = mt * 128;
    if (m0 >= cnt) return;
    int n0 = blockIdx.x * 256;

    extern __shared__ char dsm[];
    __shared__ int s_tok[128];

    int tid = threadIdx.x;
    if (tid < 128) {
        int idx = m0 + tid;
        s_tok[tid] = (idx < cnt) ? g_tok[e * TQ + idx] : -1;
    }
    __syncthreads();

    int warp = tid >> 5, lane = tid & 31;
    int wm = warp >> 2, wn = warp & 3;      // 2x4 warps, warp tile 64x64
    int g = lane >> 2, tg = lane & 3;

    int lrowA = tid >> 1, cbA = (tid & 1) * 4;
    int atok = s_tok[lrowA];
    uint32_t za = (atok >= 0) ? 16u : 0u;
    const float* aptr = g_act + (size_t)(atok >= 0 ? atok : 0) * FD + cbA * 4;
    const float* bptr = g_w2t + ((size_t)e * HD + n0 + tid) * FD;

    uint32_t sbase = s2u(dsm);
    uint32_t offA[4], offB[8];
#pragma unroll
    for (int c = 0; c < 4; c++)
        offA[c] = (uint32_t)((lrowA * 32 + (((cbA + c) ^ (lrowA & 7)) << 2)) * 4);
#pragma unroll
    for (int c = 0; c < 8; c++)
        offB[c] = (uint32_t)((tid * 32 + ((c ^ (tid & 7)) << 2)) * 4);

    int j = lane >> 3, r = lane & 7;
    uint32_t aoffA = (uint32_t)((wm * 64 + ((j & 1) << 3) + r) * 128);
    uint32_t aoffB = (uint32_t)((wn * 64 + ((j >> 1) << 3) + r) * 128);
    int cjA = j >> 1, cjB = j & 1;
    uint32_t xa[4], xb[4];
#pragma unroll
    for (int ks = 0; ks < 4; ks++) {
        xa[ks] = (uint32_t)((((2 * ks + cjA) ^ r) << 4));
        xb[ks] = (uint32_t)((((2 * ks + cjB) ^ r) << 4));
    }

    float acc[4][8][4];
#pragma unroll
    for (int mi = 0; mi < 4; mi++)
#pragma unroll
        for (int ni = 0; ni < 8; ni++)
#pragma unroll
            for (int q = 0; q < 4; q++) acc[mi][ni][q] = 0.f;

    const int NKC = FD / 32;   // 64
    LOAD_STAGE(0, 0);
    LOAD_STAGE(32, 1);

    for (int i = 0; i < NKC; i++) {
        asm volatile("cp.async.wait_group 1;" ::: "memory");
        __syncthreads();
        if (i + 2 < NKC) {
            int st = (i + 2) % 3;
            LOAD_STAGE((i + 2) * 32, st);
        } else {
            asm volatile("cp.async.commit_group;" ::: "memory");
        }
        CHUNK_MMA(i % 3);
    }

#pragma unroll
    for (int mi = 0; mi < 4; mi++) {
        int rl0 = wm * 64 + mi * 16 + g;
        int t0 = s_tok[rl0], t1 = s_tok[rl0 + 8];
        float w0 = (t0 >= 0) ? g_wt[t0] : 0.f;
        float w1v = (t1 >= 0) ? g_wt[t1] : 0.f;
#pragma unroll
        for (int ni = 0; ni < 8; ni++) {
            int col = n0 + wn * 64 + ni * 8 + tg * 2;
            float* c = acc[mi][ni];
            if (t0 >= 0)
                *(float2*)(g_y + (size_t)t0 * HD + col) =
                    make_float2(w0 * c[0], w0 * c[1]);
            if (t1 >= 0)
                *(float2*)(g_y + (size_t)t1 * HD + col) =
                    make_float2(w1v * c[2], w1v * c[3]);
        }
    }
}

// ---------------------------------------------------------------------------
// Kernel 4: combine the two expert contributions per token (full overwrite).
// ---------------------------------------------------------------------------
__global__ __launch_bounds__(256) void k_combine(float* __restrict__ out) {
    int i = blockIdx.x * 256 + threadIdx.x;
    int t = i >> 8;
    int c = i & 255;
    float4 a = ((const float4*)(g_y + (size_t)(2 * t) * HD))[c];
    float4 b = ((const float4*)(g_y + (size_t)(2 * t + 1) * HD))[c];
    ((float4*)out)[i] = make_float4(a.x + b.x, a.y + b.y, a.z + b.z, a.w + b.w);
}

// ---------------------------------------------------------------------------
// Launch
// ---------------------------------------------------------------------------
extern "C" void kernel_launch(void* const* d_in, const int* in_sizes, int n_in,
                              void* d_out, int out_size) {
    const float* hs = (const float*)d_in[0];
    const float* gw = (const float*)d_in[1];
    const float* w1 = (const float*)d_in[2];
    const float* w2 = (const float*)d_in[3];
    float* out = (float*)d_out;
    float* logits = (out_size >= TQ * HD + TQ * NE) ? out + (size_t)TQ * HD
                                                    : nullptr;

    static const int DSMEM = 3 * (int)STAGE_BYTES;   // 144 KB
    static bool attr_done = false;
    if (!attr_done) {
        cudaFuncSetAttribute(k_ffn1, cudaFuncAttributeMaxDynamicSharedMemorySize, DSMEM);
        cudaFuncSetAttribute(k_ffn2, cudaFuncAttributeMaxDynamicSharedMemorySize, DSMEM);
        attr_done = true;
    }

    float* w1t; cudaGetSymbolAddress((void**)&w1t, g_w1t);
    float* w2t; cudaGetSymbolAddress((void**)&w2t, g_w2t);
    float* hst; cudaGetSymbolAddress((void**)&hst, g_hst);

    k_zero<<<1, 32>>>();
    k_router<<<TQ / 8, 256>>>(hs, gw, logits);
    k_cvt<<<(NE * 2 * FD * HD / 4) / 256, 256>>>((const float4*)w1, (float4*)w1t,
                                                 NE * 2 * FD * HD / 4);
    k_cvt<<<(NE * HD * FD / 4) / 256, 256>>>((const float4*)w2, (float4*)w2t,
                                             NE * HD * FD / 4);
    k_cvt<<<(TQ * HD / 4) / 256, 256>>>((const float4*)hs, (float4*)hst,
                                        TQ * HD / 4);
    k_ffn1<<<dim3(FD / 128, NE * 32), 256, DSMEM>>>();
    k_ffn2<<<dim3(HD / 256, NE * 32), 256, DSMEM>>>();
    k_combine<<<(TQ * HD / 4) / 256, 256>>>(out);
}

// round 6
// speedup vs baseline: 1.2634x; 1.2634x over previous
#include <cuda_runtime.h>
#include <cstdint>

// Problem constants
#define TQ 4096   // tokens
#define HD 1024   // hidden
#define FD 2048   // ffn dim (w1 rows: [gate(0..FD), up(FD..2FD)])
#define NE 8      // experts
#define NK 2      // top-k

// ---------------------------------------------------------------------------
// Scratch (device globals; runtime allocation is forbidden)
// ---------------------------------------------------------------------------
__device__ int   g_counts[NE];
__device__ int   g_tok[NE * TQ];
__device__ float g_wt[TQ * NK];
__device__ float g_act[(size_t)TQ * NK * FD];        // tf32-rounded silu(g)*u
__device__ float g_y[(size_t)TQ * NK * HD];
__device__ float g_hst[(size_t)TQ * HD];             // tf32-rounded hs
__device__ float g_w1t[(size_t)NE * 2 * FD * HD];    // tf32-rounded w1
__device__ float g_w2t[(size_t)NE * HD * FD];        // tf32-rounded w2

// ---------------------------------------------------------------------------
// Helpers
// ---------------------------------------------------------------------------
__device__ __forceinline__ uint32_t f2tf(float x) {
    uint32_t r;
    asm("cvt.rna.tf32.f32 %0, %1;" : "=r"(r) : "f"(x));
    return r;
}
__device__ __forceinline__ uint32_t s2u(const void* p) {
    uint32_t a;
    asm("{ .reg .u64 t; cvta.to.shared.u64 t, %1; cvt.u32.u64 %0, t; }"
        : "=r"(a) : "l"(p));
    return a;
}
__device__ __forceinline__ void mma_tf32(float* c, const uint32_t* a,
                                         uint32_t b0, uint32_t b1) {
    asm volatile(
        "mma.sync.aligned.m16n8k8.row.col.f32.tf32.tf32.f32 "
        "{%0,%1,%2,%3}, {%4,%5,%6,%7}, {%8,%9}, {%0,%1,%2,%3};"
        : "+f"(c[0]), "+f"(c[1]), "+f"(c[2]), "+f"(c[3])
        : "r"(a[0]), "r"(a[1]), "r"(a[2]), "r"(a[3]), "r"(b0), "r"(b1));
}
// ldmatrix x4 over b16: with 16B rows = 4 tf32, lane receives tf32
// element [lane/4][lane%4] of each 8x4 matrix — exactly the mma frag layout.
__device__ __forceinline__ void ldsm4(uint32_t* r, uint32_t addr) {
    asm volatile("ldmatrix.sync.aligned.m8n8.x4.shared.b16 {%0,%1,%2,%3}, [%4];"
                 : "=r"(r[0]), "=r"(r[1]), "=r"(r[2]), "=r"(r[3]) : "r"(addr));
}
__device__ __forceinline__ float silu(float x) {
    return x / (1.0f + __expf(-x));
}

// 16B cp.async with zero-fill when sz==0 (invalid A rows)
#define CPA16(sa, ga, sz)                                                      \
    asm volatile("cp.async.cg.shared.global [%0], [%1], 16, %2;"               \
                 :: "r"(sa), "l"(ga), "r"(sz) : "memory")

// Load one 128x32 A tile + 128x32 B tile into stage ST (32KB/stage), swizzled:
// physical 16B-chunk = chunk ^ (row & 7). Commits one cp.async group.
#define LOAD_STAGE(KC, ST) do {                                                \
    uint32_t _b = sbase + (uint32_t)(ST) * 32768u;                             \
    const float* _a = aptr + (KC);                                             \
    const float* _w = bptr + (KC);                                             \
    _Pragma("unroll")                                                          \
    for (int _c = 0; _c < 4; _c++) {                                           \
        CPA16(_b + offs[_c], _a + _c * 4, za);                                 \
        CPA16(_b + 16384u + offs[_c], _w + _c * 4, 16u);                       \
    }                                                                          \
    asm volatile("cp.async.commit_group;" ::: "memory");                       \
} while (0)

// Fragment-load + MMA for one K-chunk (shared by both FFN kernels).
#define CHUNK_MMA(IST) do {                                                    \
    uint32_t _sA = sbase + (uint32_t)(IST) * 32768u;                           \
    uint32_t _sB = _sA + 16384u;                                               \
    _Pragma("unroll")                                                          \
    for (int ks = 0; ks < 4; ks++) {                                           \
        uint32_t br[4][4];                                                     \
        _Pragma("unroll")                                                      \
        for (int nip = 0; nip < 4; nip++)                                      \
            ldsm4(br[nip], _sB + aoffB + nip * 2048u + xb[ks]);                \
        uint32_t ar[2][4];                                                     \
        _Pragma("unroll")                                                      \
        for (int mi = 0; mi < 2; mi++)                                         \
            ldsm4(ar[mi], _sA + aoffA + mi * 2048u + xa[ks]);                  \
        _Pragma("unroll")                                                      \
        for (int mi = 0; mi < 2; mi++)                                         \
            _Pragma("unroll")                                                  \
            for (int ni = 0; ni < 8; ni++)                                     \
                mma_tf32(acc[mi][ni], ar[mi],                                  \
                         br[ni >> 1][2 * (ni & 1)],                            \
                         br[ni >> 1][2 * (ni & 1) + 1]);                       \
    }                                                                          \
} while (0)

// ---------------------------------------------------------------------------
// Kernel 0b: tf32-round a tensor into scratch
// ---------------------------------------------------------------------------
__global__ __launch_bounds__(256) void k_cvt(const float4* __restrict__ src,
                                             float4* __restrict__ dst, int n4) {
    int i = blockIdx.x * 256 + threadIdx.x;
    if (i >= n4) return;
    float4 v = src[i];
    float4 o;
    o.x = __uint_as_float(f2tf(v.x));
    o.y = __uint_as_float(f2tf(v.y));
    o.z = __uint_as_float(f2tf(v.z));
    o.w = __uint_as_float(f2tf(v.w));
    dst[i] = o;
}

// ---------------------------------------------------------------------------
// Kernel 1: router. One warp per token.
// ---------------------------------------------------------------------------
__global__ __launch_bounds__(256) void k_router(const float* __restrict__ hs,
                                                const float* __restrict__ gw,
                                                float* __restrict__ logits_out) {
    __shared__ float sg[NE * HD];
    int tid = threadIdx.x;
    for (int i = tid; i < NE * HD; i += 256) sg[i] = gw[i];
    __syncthreads();

    int warp = tid >> 5, lane = tid & 31;
    int t = blockIdx.x * 8 + warp;
    const float* x = hs + (size_t)t * HD;

    float acc[NE];
#pragma unroll
    for (int e = 0; e < NE; e++) acc[e] = 0.f;
    for (int j = lane; j < HD; j += 32) {
        float xv = x[j];
#pragma unroll
        for (int e = 0; e < NE; e++) acc[e] += xv * sg[e * HD + j];
    }
#pragma unroll
    for (int e = 0; e < NE; e++) {
#pragma unroll
        for (int off = 16; off; off >>= 1)
            acc[e] += __shfl_xor_sync(0xffffffffu, acc[e], off);
    }

    if (lane == 0) {
        if (logits_out) {
#pragma unroll
            for (int e = 0; e < NE; e++) logits_out[(size_t)t * NE + e] = acc[e];
        }
        float m1 = acc[0]; int i0 = 0;
#pragma unroll
        for (int e = 1; e < NE; e++) if (acc[e] > m1) { m1 = acc[e]; i0 = e; }
        float m2 = -3.4e38f; int i1 = 0;
#pragma unroll
        for (int e = 0; e < NE; e++)
            if (e != i0 && acc[e] > m2) { m2 = acc[e]; i1 = e; }
        float e2v = __expf(m2 - m1);
        float inv = 1.0f / (1.0f + e2v);

        int p0 = atomicAdd(&g_counts[i0], 1);
        g_tok[i0 * TQ + p0] = t * 2;
        g_wt[t * 2] = inv;
        int p1 = atomicAdd(&g_counts[i1], 1);
        g_tok[i1 * TQ + p1] = t * 2 + 1;
        g_wt[t * 2 + 1] = e2v * inv;
    }
}

// ---------------------------------------------------------------------------
// Kernel 2: FFN1 grouped GEMM with fused SiLU*up.
// 128 rows x 128 mma cols (gate/up interleaved). 3-stage cp.async pipeline,
// ldmatrix fragment loads. grid = (FD/64 = 32, NE*32), 256 threads, 2 CTA/SM.
// ---------------------------------------------------------------------------
__global__ __launch_bounds__(256, 2) void k_ffn1() {
    int e  = blockIdx.y >> 5;
    int mt = blockIdx.y & 31;
    int cnt = g_counts[e];
    int m0 = mt * 128;
    if (m0 >= cnt) return;
    int n0 = blockIdx.x * 64;

    extern __shared__ char dsm[];
    __shared__ int s_tok[128];

    int tid = threadIdx.x;
    if (tid < 128) {
        int idx = m0 + tid;
        s_tok[tid] = (idx < cnt) ? g_tok[e * TQ + idx] : -1;
    }
    __syncthreads();

    int warp = tid >> 5, lane = tid & 31;
    int wm = warp >> 1, wn = warp & 1;      // 4x2 warps, warp tile 32x64
    int g = lane >> 2, tg = lane & 3;

    // loader: 2 threads per tile row, 4 x 16B chunks each
    int lrow = tid >> 1, lcb = (tid & 1) * 4;
    int atok = s_tok[lrow];
    uint32_t za = (atok >= 0) ? 16u : 0u;
    const float* aptr = g_hst + (size_t)(atok >= 0 ? (atok >> 1) : 0) * HD + lcb * 4;
    int wrow = (lrow & 1) ? (FD + n0 + (lrow >> 1)) : (n0 + (lrow >> 1));
    const float* bptr = g_w1t + ((size_t)e * 2 * FD + wrow) * HD + lcb * 4;

    uint32_t sbase = s2u(dsm);
    uint32_t offs[4];
#pragma unroll
    for (int c = 0; c < 4; c++)
        offs[c] = (uint32_t)((lrow * 32 + (((lcb + c) ^ (lrow & 7)) << 2)) * 4);

    // ldmatrix per-lane address components
    int j = lane >> 3, r = lane & 7;
    uint32_t aoffA = (uint32_t)((wm * 32 + ((j & 1) << 3) + r) * 128);
    uint32_t aoffB = (uint32_t)((wn * 64 + ((j >> 1) << 3) + r) * 128);
    int cjA = j >> 1, cjB = j & 1;
    uint32_t xa[4], xb[4];
#pragma unroll
    for (int ks = 0; ks < 4; ks++) {
        xa[ks] = (uint32_t)((((2 * ks + cjA) ^ r) << 4));
        xb[ks] = (uint32_t)((((2 * ks + cjB) ^ r) << 4));
    }

    float acc[2][8][4];
#pragma unroll
    for (int mi = 0; mi < 2; mi++)
#pragma unroll
        for (int ni = 0; ni < 8; ni++)
#pragma unroll
            for (int q = 0; q < 4; q++) acc[mi][ni][q] = 0.f;

    const int NKC = HD / 32;   // 32
    LOAD_STAGE(0, 0);
    LOAD_STAGE(32, 1);

    for (int i = 0; i < NKC; i++) {
        asm volatile("cp.async.wait_group 1;" ::: "memory");
        __syncthreads();
        if (i + 2 < NKC) {
            int st = (i + 2) % 3;
            LOAD_STAGE((i + 2) * 32, st);
        } else {
            asm volatile("cp.async.commit_group;" ::: "memory");
        }
        CHUNK_MMA(i % 3);
    }

    // Epilogue: even mma col = gate, odd = up; write tf32-rounded activation.
#pragma unroll
    for (int mi = 0; mi < 2; mi++) {
        int rl0 = wm * 32 + mi * 16 + g;
        int t0 = s_tok[rl0], t1 = s_tok[rl0 + 8];
#pragma unroll
        for (int ni = 0; ni < 8; ni++) {
            int colg = n0 + wn * 32 + ni * 4 + tg;
            float* c = acc[mi][ni];
            if (t0 >= 0)
                g_act[(size_t)t0 * FD + colg] =
                    __uint_as_float(f2tf(silu(c[0]) * c[1]));
            if (t1 >= 0)
                g_act[(size_t)t1 * FD + colg] =
                    __uint_as_float(f2tf(silu(c[2]) * c[3]));
        }
    }
}

// ---------------------------------------------------------------------------
// Kernel 3: FFN2 grouped GEMM (act @ w2[e]^T), scaled by combine weight.
// grid = (HD/128 = 8, NE*32), 256 threads, same pipeline.
// ---------------------------------------------------------------------------
__global__ __launch_bounds__(256, 2) void k_ffn2() {
    int e  = blockIdx.y >> 5;
    int mt = blockIdx.y & 31;
    int cnt = g_counts[e];
    int m0 = mt * 128;
    if (m0 >= cnt) return;
    int n0 = blockIdx.x * 128;

    extern __shared__ char dsm[];
    __shared__ int s_tok[128];

    int tid = threadIdx.x;
    if (tid < 128) {
        int idx = m0 + tid;
        s_tok[tid] = (idx < cnt) ? g_tok[e * TQ + idx] : -1;
    }
    __syncthreads();

    int warp = tid >> 5, lane = tid & 31;
    int wm = warp >> 1, wn = warp & 1;
    int g = lane >> 2, tg = lane & 3;

    int lrow = tid >> 1, lcb = (tid & 1) * 4;
    int atok = s_tok[lrow];
    uint32_t za = (atok >= 0) ? 16u : 0u;
    const float* aptr = g_act + (size_t)(atok >= 0 ? atok : 0) * FD + lcb * 4;
    const float* bptr = g_w2t + ((size_t)e * HD + n0 + lrow) * FD + lcb * 4;

    uint32_t sbase = s2u(dsm);
    uint32_t offs[4];
#pragma unroll
    for (int c = 0; c < 4; c++)
        offs[c] = (uint32_t)((lrow * 32 + (((lcb + c) ^ (lrow & 7)) << 2)) * 4);

    int j = lane >> 3, r = lane & 7;
    uint32_t aoffA = (uint32_t)((wm * 32 + ((j & 1) << 3) + r) * 128);
    uint32_t aoffB = (uint32_t)((wn * 64 + ((j >> 1) << 3) + r) * 128);
    int cjA = j >> 1, cjB = j & 1;
    uint32_t xa[4], xb[4];
#pragma unroll
    for (int ks = 0; ks < 4; ks++) {
        xa[ks] = (uint32_t)((((2 * ks + cjA) ^ r) << 4));
        xb[ks] = (uint32_t)((((2 * ks + cjB) ^ r) << 4));
    }

    float acc[2][8][4];
#pragma unroll
    for (int mi = 0; mi < 2; mi++)
#pragma unroll
        for (int ni = 0; ni < 8; ni++)
#pragma unroll
            for (int q = 0; q < 4; q++) acc[mi][ni][q] = 0.f;

    const int NKC = FD / 32;   // 64
    LOAD_STAGE(0, 0);
    LOAD_STAGE(32, 1);

    for (int i = 0; i < NKC; i++) {
        asm volatile("cp.async.wait_group 1;" ::: "memory");
        __syncthreads();
        if (i + 2 < NKC) {
            int st = (i + 2) % 3;
            LOAD_STAGE((i + 2) * 32, st);
        } else {
            asm volatile("cp.async.commit_group;" ::: "memory");
        }
        CHUNK_MMA(i % 3);
    }

#pragma unroll
    for (int mi = 0; mi < 2; mi++) {
        int rl0 = wm * 32 + mi * 16 + g;
        int t0 = s_tok[rl0], t1 = s_tok[rl0 + 8];
        float w0 = (t0 >= 0) ? g_wt[t0] : 0.f;
        float w1v = (t1 >= 0) ? g_wt[t1] : 0.f;
#pragma unroll
        for (int ni = 0; ni < 8; ni++) {
            int col = n0 + wn * 64 + ni * 8 + tg * 2;
            float* c = acc[mi][ni];
            if (t0 >= 0)
                *(float2*)(g_y + (size_t)t0 * HD + col) =
                    make_float2(w0 * c[0], w0 * c[1]);
            if (t1 >= 0)
                *(float2*)(g_y + (size_t)t1 * HD + col) =
                    make_float2(w1v * c[2], w1v * c[3]);
        }
    }
}

// ---------------------------------------------------------------------------
// Kernel 4: combine the two expert contributions per token (full overwrite).
// ---------------------------------------------------------------------------
__global__ __launch_bounds__(256) void k_combine(float* __restrict__ out) {
    int i = blockIdx.x * 256 + threadIdx.x;
    int t = i >> 8;
    int c = i & 255;
    float4 a = ((const float4*)(g_y + (size_t)(2 * t) * HD))[c];
    float4 b = ((const float4*)(g_y + (size_t)(2 * t + 1) * HD))[c];
    ((float4*)out)[i] = make_float4(a.x + b.x, a.y + b.y, a.z + b.z, a.w + b.w);
}

// ---------------------------------------------------------------------------
// Launch. Kernel-launch order matters for profiling: ncu captures kernel
// index 3, which is k_ffn1 here (router=0, cvt_w1=1, cvt_hs=2, ffn1=3).
// ---------------------------------------------------------------------------
extern "C" void kernel_launch(void* const* d_in, const int* in_sizes, int n_in,
                              void* d_out, int out_size) {
    const float* hs = (const float*)d_in[0];
    const float* gw = (const float*)d_in[1];
    const float* w1 = (const float*)d_in[2];
    const float* w2 = (const float*)d_in[3];
    float* out = (float*)d_out;
    float* logits = (out_size >= TQ * HD + TQ * NE) ? out + (size_t)TQ * HD
                                                    : nullptr;

    static const int DSMEM = 98304;  // 3 stages x (16KB A + 16KB B)
    static bool attr_done = false;
    if (!attr_done) {
        cudaFuncSetAttribute(k_ffn1, cudaFuncAttributeMaxDynamicSharedMemorySize, DSMEM);
        cudaFuncSetAttribute(k_ffn2, cudaFuncAttributeMaxDynamicSharedMemorySize, DSMEM);
        attr_done = true;
    }

    float* w1t; cudaGetSymbolAddress((void**)&w1t, g_w1t);
    float* w2t; cudaGetSymbolAddress((void**)&w2t, g_w2t);
    float* hst; cudaGetSymbolAddress((void**)&hst, g_hst);
    int*   cnts; cudaGetSymbolAddress((void**)&cnts, g_counts);

    cudaMemsetAsync(cnts, 0, NE * sizeof(int));                       // node, not kernel
    k_router<<<TQ / 8, 256>>>(hs, gw, logits);                        // kernel 0
    k_cvt<<<(NE * 2 * FD * HD / 4) / 256, 256>>>((const float4*)w1,   // kernel 1
                                                 (float4*)w1t, NE * 2 * FD * HD / 4);
    k_cvt<<<(TQ * HD / 4) / 256, 256>>>((const float4*)hs,            // kernel 2
                                        (float4*)hst, TQ * HD / 4);
    k_ffn1<<<dim3(FD / 64, NE * 32), 256, DSMEM>>>();                 // kernel 3 (profiled)
    k_cvt<<<(NE * HD * FD / 4) / 256, 256>>>((const float4*)w2,       // kernel 4
                                             (float4*)w2t, NE * HD * FD / 4);
    k_ffn2<<<dim3(HD / 128, NE * 32), 256, DSMEM>>>();                // kernel 5
    k_combine<<<(TQ * HD / 4) / 256, 256>>>(out);                     // kernel 6
}